// round 4
// baseline (speedup 1.0000x reference)
#include <cuda_runtime.h>
#include <cuda_bf16.h>
#include <cstdint>

#define GRAPHS 512
#define CDIM 256

// ---- device scratch (no allocations allowed) ----
__device__ uint2 g_Bfrag[2 * 16 * 32 * 32];   // 256 KB: bf16 B fragments, [s][kt][nt][lane]
__device__ float g_sums[GRAPHS * CDIM];       // 512 KB: pooled sums
__device__ int   g_cnt[GRAPHS];

static __device__ __forceinline__ uint32_t packbf(float a, float b) {
    __nv_bfloat162 h = __float22bfloat162_rn(make_float2(a, b));
    return *reinterpret_cast<uint32_t*>(&h);
}

// ---------------------------------------------------------------------------
__global__ void zero_sums_kernel() {
    int i = blockIdx.x * blockDim.x + threadIdx.x;
    if (i < GRAPHS * CDIM) g_sums[i] = 0.f;
}

// Pack W_gate (s=0) and W_lin (s=1) into m16n8k16 B-fragment order:
// idx = ((s*16 + kt)*32 + nt)*32 + lane
// n = nt*8 + lane/4, k0 = kt*16 + (lane%4)*2
// v.x = bf16x2(W[k0][n], W[k0+1][n]); v.y = bf16x2(W[k0+8][n], W[k0+9][n])
__global__ void prep_weights_kernel(const float* __restrict__ Wg,
                                    const float* __restrict__ Wl) {
    int i = blockIdx.x * blockDim.x + threadIdx.x;
    if (i >= 2 * 16 * 32 * 32) return;
    int lane = i & 31;
    int nt   = (i >> 5) & 31;
    int kt   = (i >> 10) & 15;
    int s    = i >> 14;
    const float* W = s ? Wl : Wg;
    int n  = nt * 8 + (lane >> 2);
    int k0 = kt * 16 + (lane & 3) * 2;
    uint2 v;
    v.x = packbf(W[(k0 + 0) * CDIM + n], W[(k0 + 1) * CDIM + n]);
    v.y = packbf(W[(k0 + 8) * CDIM + n], W[(k0 + 9) * CDIM + n]);
    g_Bfrag[i] = v;
}

// batch is sorted int32: counts via binary search, no atomics.
__global__ void counts_kernel(const int* __restrict__ batch, int N) {
    int g = threadIdx.x;
    if (g >= GRAPHS) return;
    int k0 = g, k1 = g + 1;
    int lo = 0, hi = N;
    while (lo < hi) { int m = (lo + hi) >> 1; if (batch[m] < k0) lo = m + 1; else hi = m; }
    int a = lo;
    hi = N;
    while (lo < hi) { int m = (lo + hi) >> 1; if (batch[m] < k1) lo = m + 1; else hi = m; }
    g_cnt[g] = lo - a;
}

// ---------------------------------------------------------------------------
static __device__ __forceinline__ void mma_bf16(float acc[4],
                                                uint32_t a0, uint32_t a1,
                                                uint32_t a2, uint32_t a3,
                                                uint32_t b0, uint32_t b1) {
    asm volatile(
        "mma.sync.aligned.m16n8k16.row.col.f32.bf16.bf16.f32 "
        "{%0,%1,%2,%3}, {%4,%5,%6,%7}, {%8,%9}, {%0,%1,%2,%3};\n"
        : "+f"(acc[0]), "+f"(acc[1]), "+f"(acc[2]), "+f"(acc[3])
        : "r"(a0), "r"(a1), "r"(a2), "r"(a3), "r"(b0), "r"(b1));
}

// Fused: x tile -> bf16 smem -> gate GEMM (regs) -> cross-warp softmax ->
// state GEMM -> gated product -> bf16 staging in xs -> segment reduce -> atomics.
// Block: 64 nodes, 256 threads (8 warps: 4 row-strips x 2 col-halves).
// Static shared only (~37 KB) — no dynamic smem, no cudaFuncSetAttribute.
#define XS_STRIDE 132                  // 128 uint32 + 4 pad
__global__ __launch_bounds__(256) void main_kernel(
    const float* __restrict__ x, const int* __restrict__ batch,
    const float* __restrict__ b_lin, const float* __restrict__ b_gate, int N) {
    __shared__ uint32_t xs[64 * XS_STRIDE];   // 33792 B
    __shared__ float    bias[512];            // gate 0..255, lin 256..511
    __shared__ float    redmax[128];          // [row][half]
    __shared__ float    redsum[128];
    __shared__ int      bid[64];

    const int tid   = threadIdx.x;
    const int node0 = blockIdx.x * 64;

    // load x tile as packed bf16x2 (coalesced float2 reads)
    for (int i = tid; i < 64 * 128; i += 256) {
        int r = i >> 7, cp = i & 127;
        float2 v = make_float2(0.f, 0.f);
        if (node0 + r < N)
            v = reinterpret_cast<const float2*>(x)[(size_t)(node0 + r) * 128 + cp];
        xs[r * XS_STRIDE + cp] = packbf(v.x, v.y);
    }
    bias[tid]       = b_gate[tid];
    bias[256 + tid] = b_lin[tid];
    if (tid < 64) {
        int nd = node0 + tid;
        bid[tid] = (nd < N) ? batch[nd] : -1;
    }
    __syncthreads();

    const int lane = tid & 31, w = tid >> 5;
    const int wr = w >> 1, wc = w & 1;
    const int r0 = wr * 16, gid = lane >> 2, tg = lane & 3;
    const int ra = r0 + gid, rb = ra + 8;
    const int rowA0 = ra * XS_STRIDE;
    const int rowA1 = rb * XS_STRIDE;

    // ================= GEMM 1: gate logits (held in registers) ==============
    float gate[16][4];
    #pragma unroll
    for (int t = 0; t < 16; t++) { gate[t][0] = gate[t][1] = gate[t][2] = gate[t][3] = 0.f; }
    for (int kt = 0; kt < 16; kt++) {
        uint32_t a0 = xs[rowA0 + kt * 8 + tg];
        uint32_t a1 = xs[rowA1 + kt * 8 + tg];
        uint32_t a2 = xs[rowA0 + kt * 8 + 4 + tg];
        uint32_t a3 = xs[rowA1 + kt * 8 + 4 + tg];
        const uint2* bp = g_Bfrag + ((size_t)kt * 32 + wc * 16) * 32 + lane;
        #pragma unroll
        for (int t = 0; t < 16; t++) {
            uint2 bq = bp[t * 32];
            mma_bf16(gate[t], a0, a1, a2, a3, bq.x, bq.y);
        }
    }
    // add gate bias
    #pragma unroll
    for (int t = 0; t < 16; t++) {
        int c = wc * 128 + t * 8 + tg * 2;
        gate[t][0] += bias[c];     gate[t][1] += bias[c + 1];
        gate[t][2] += bias[c];     gate[t][3] += bias[c + 1];
    }

    // ================= cross-warp row softmax ================================
    {
        float mxa = -1e30f, mxb = -1e30f;
        #pragma unroll
        for (int t = 0; t < 16; t++) {
            mxa = fmaxf(mxa, fmaxf(gate[t][0], gate[t][1]));
            mxb = fmaxf(mxb, fmaxf(gate[t][2], gate[t][3]));
        }
        mxa = fmaxf(mxa, __shfl_xor_sync(0xffffffffu, mxa, 1));
        mxa = fmaxf(mxa, __shfl_xor_sync(0xffffffffu, mxa, 2));
        mxb = fmaxf(mxb, __shfl_xor_sync(0xffffffffu, mxb, 1));
        mxb = fmaxf(mxb, __shfl_xor_sync(0xffffffffu, mxb, 2));
        if (tg == 0) { redmax[ra * 2 + wc] = mxa; redmax[rb * 2 + wc] = mxb; }
    }
    __syncthreads();
    float invA, invB;
    {
        float mA = fmaxf(redmax[ra * 2], redmax[ra * 2 + 1]);
        float mB = fmaxf(redmax[rb * 2], redmax[rb * 2 + 1]);
        float sa = 0.f, sb = 0.f;
        #pragma unroll
        for (int t = 0; t < 16; t++) {
            gate[t][0] = __expf(gate[t][0] - mA); sa += gate[t][0];
            gate[t][1] = __expf(gate[t][1] - mA); sa += gate[t][1];
            gate[t][2] = __expf(gate[t][2] - mB); sb += gate[t][2];
            gate[t][3] = __expf(gate[t][3] - mB); sb += gate[t][3];
        }
        sa += __shfl_xor_sync(0xffffffffu, sa, 1);
        sa += __shfl_xor_sync(0xffffffffu, sa, 2);
        sb += __shfl_xor_sync(0xffffffffu, sb, 1);
        sb += __shfl_xor_sync(0xffffffffu, sb, 2);
        if (tg == 0) { redsum[ra * 2 + wc] = sa; redsum[rb * 2 + wc] = sb; }
        __syncthreads();
        invA = 1.f / (redsum[ra * 2] + redsum[ra * 2 + 1]);
        invB = 1.f / (redsum[rb * 2] + redsum[rb * 2 + 1]);
    }

    // ================= GEMM 2: states =======================================
    float acc[16][4];
    #pragma unroll
    for (int t = 0; t < 16; t++) { acc[t][0] = acc[t][1] = acc[t][2] = acc[t][3] = 0.f; }
    for (int kt = 0; kt < 16; kt++) {
        uint32_t a0 = xs[rowA0 + kt * 8 + tg];
        uint32_t a1 = xs[rowA1 + kt * 8 + tg];
        uint32_t a2 = xs[rowA0 + kt * 8 + 4 + tg];
        uint32_t a3 = xs[rowA1 + kt * 8 + 4 + tg];
        const uint2* bp = g_Bfrag + ((size_t)(16 + kt) * 32 + wc * 16) * 32 + lane;
        #pragma unroll
        for (int t = 0; t < 16; t++) {
            uint2 bq = bp[t * 32];
            mma_bf16(acc[t], a0, a1, a2, a3, bq.x, bq.y);
        }
    }
    __syncthreads();   // all warps done reading xs; safe to overwrite

    // gated product, staged into xs as bf16x2
    #pragma unroll
    for (int t = 0; t < 16; t++) {
        int c  = wc * 128 + t * 8 + tg * 2;
        int cp = c >> 1;
        float b0 = bias[256 + c], b1 = bias[256 + c + 1];
        float v0 = (acc[t][0] + b0) * gate[t][0] * invA;
        float v1 = (acc[t][1] + b1) * gate[t][1] * invA;
        float v2 = (acc[t][2] + b0) * gate[t][2] * invB;
        float v3 = (acc[t][3] + b1) * gate[t][3] * invB;
        xs[ra * XS_STRIDE + cp] = packbf(v0, v1);
        xs[rb * XS_STRIDE + cp] = packbf(v2, v3);
    }
    __syncthreads();

    // ================= segment reduce (sorted batch), few atomics ===========
    {
        const int cp = tid >> 1, hi = tid & 1;
        float run = 0.f;
        int cur = -1;
        for (int r = 0; r < 64; r++) {
            int g = bid[r];
            if (g != cur) {
                if (cur >= 0) atomicAdd(&g_sums[cur * CDIM + tid], run);
                run = 0.f;
                cur = g;
            }
            if (g >= 0) {
                uint32_t u = xs[r * XS_STRIDE + cp];
                __nv_bfloat162 h = *reinterpret_cast<__nv_bfloat162*>(&u);
                run += hi ? __bfloat162float(h.y) : __bfloat162float(h.x);
            }
        }
        if (cur >= 0) atomicAdd(&g_sums[cur * CDIM + tid], run);
    }
}

// out[g][c] = b_fin[c] + sum_k (sums[g][k]/max(cnt,1)) * W_fin[k][c]
__global__ void final_kernel(const float* __restrict__ W_fin,
                             const float* __restrict__ b_fin,
                             float* __restrict__ out) {
    __shared__ float mrow[CDIM];
    int g = blockIdx.x, t = threadIdx.x;
    float invc = 1.f / fmaxf((float)g_cnt[g], 1.f);
    mrow[t] = g_sums[g * CDIM + t] * invc;
    __syncthreads();
    float a = b_fin[t];
    #pragma unroll 8
    for (int k = 0; k < CDIM; k++) a = fmaf(mrow[k], W_fin[k * CDIM + t], a);
    out[g * CDIM + t] = a;
}

// ---------------------------------------------------------------------------
extern "C" void kernel_launch(void* const* d_in, const int* in_sizes, int n_in,
                              void* d_out, int out_size) {
    const float* x      = (const float*)d_in[0];
    // d_in[1] = edge_index (int32) : unused by the reference computation
    const int*   batch  = (const int*)d_in[2];     // jax x64 disabled -> int32
    const float* W_lin  = (const float*)d_in[3];
    const float* b_lin  = (const float*)d_in[4];
    const float* W_gate = (const float*)d_in[5];
    const float* b_gate = (const float*)d_in[6];
    const float* W_fin  = (const float*)d_in[7];
    const float* b_fin  = (const float*)d_in[8];
    float*       out    = (float*)d_out;

    int N = in_sizes[0] / CDIM;

    zero_sums_kernel<<<(GRAPHS * CDIM + 255) / 256, 256>>>();
    prep_weights_kernel<<<(2 * 16 * 32 * 32 + 255) / 256, 256>>>(W_gate, W_lin);

    int blocks = (N + 63) / 64;
    main_kernel<<<blocks, 256>>>(x, batch, b_lin, b_gate, N);

    counts_kernel<<<1, GRAPHS>>>(batch, N);
    final_kernel<<<GRAPHS, CDIM>>>(W_fin, b_fin, out);
}

// round 5
// speedup vs baseline: 1.1869x; 1.1869x over previous
#include <cuda_runtime.h>
#include <cuda_bf16.h>
#include <cstdint>

#define GRAPHS 512
#define CDIM 256

// ---- device scratch (no allocations allowed) ----
__device__ uint2 g_Bfrag[2 * 16 * 32 * 32];   // 256 KB: bf16 B fragments, [s][kt][nt][lane]
__device__ float g_sums[GRAPHS * CDIM];       // 512 KB: pooled sums
__device__ int   g_cnt[GRAPHS];

static __device__ __forceinline__ uint32_t packbf(float a, float b) {
    __nv_bfloat162 h = __float22bfloat162_rn(make_float2(a, b));
    return *reinterpret_cast<uint32_t*>(&h);
}

// ---------------------------------------------------------------------------
__global__ void zero_sums_kernel() {
    int i = blockIdx.x * blockDim.x + threadIdx.x;
    if (i < GRAPHS * CDIM) g_sums[i] = 0.f;
}

// Pack W_gate (s=0) and W_lin (s=1) into m16n8k16 B-fragment order:
// idx = ((s*16 + kt)*32 + nt)*32 + lane
// n = nt*8 + lane/4, k0 = kt*16 + (lane%4)*2
__global__ void prep_weights_kernel(const float* __restrict__ Wg,
                                    const float* __restrict__ Wl) {
    int i = blockIdx.x * blockDim.x + threadIdx.x;
    if (i >= 2 * 16 * 32 * 32) return;
    int lane = i & 31;
    int nt   = (i >> 5) & 31;
    int kt   = (i >> 10) & 15;
    int s    = i >> 14;
    const float* W = s ? Wl : Wg;
    int n  = nt * 8 + (lane >> 2);
    int k0 = kt * 16 + (lane & 3) * 2;
    uint2 v;
    v.x = packbf(W[(k0 + 0) * CDIM + n], W[(k0 + 1) * CDIM + n]);
    v.y = packbf(W[(k0 + 8) * CDIM + n], W[(k0 + 9) * CDIM + n]);
    g_Bfrag[i] = v;
}

// batch sorted int32: counts via binary search; spread over blocks.
__global__ void counts_kernel(const int* __restrict__ batch, int N) {
    int g = blockIdx.x * blockDim.x + threadIdx.x;
    if (g >= GRAPHS) return;
    int k0 = g, k1 = g + 1;
    int lo = 0, hi = N;
    while (lo < hi) { int m = (lo + hi) >> 1; if (batch[m] < k0) lo = m + 1; else hi = m; }
    int a = lo;
    hi = N;
    while (lo < hi) { int m = (lo + hi) >> 1; if (batch[m] < k1) lo = m + 1; else hi = m; }
    g_cnt[g] = lo - a;
}

// ---------------------------------------------------------------------------
static __device__ __forceinline__ void mma_bf16(float acc[4],
                                                uint32_t a0, uint32_t a1,
                                                uint32_t a2, uint32_t a3,
                                                uint32_t b0, uint32_t b1) {
    asm volatile(
        "mma.sync.aligned.m16n8k16.row.col.f32.bf16.bf16.f32 "
        "{%0,%1,%2,%3}, {%4,%5,%6,%7}, {%8,%9}, {%0,%1,%2,%3};\n"
        : "+f"(acc[0]), "+f"(acc[1]), "+f"(acc[2]), "+f"(acc[3])
        : "r"(a0), "r"(a1), "r"(a2), "r"(a3), "r"(b0), "r"(b1));
}

static __device__ __forceinline__ void cp_async16(uint32_t smem_dst, const void* gsrc) {
    asm volatile("cp.async.cg.shared.global [%0], [%1], 16;\n"
                 :: "r"(smem_dst), "l"(gsrc));
}
static __device__ __forceinline__ void cp_commit() {
    asm volatile("cp.async.commit_group;\n");
}
static __device__ __forceinline__ void cp_wait2() {
    asm volatile("cp.async.wait_group 2;\n");
}

// Fused: x tile -> bf16 smem -> gate GEMM -> cross-warp softmax -> state GEMM
// -> gated product -> bf16 staging in xs -> segment reduce -> atomics.
// B fragments staged through smem with a 3-deep cp.async pipeline (8 KB slabs).
// Block: 64 nodes, 256 threads (8 warps: 4 row-strips x 2 col-halves).
#define XS_STRIDE 132                  // 128 uint32 + 4 pad
#define SLAB_U2   1024                 // 32 nt * 32 lanes, uint2 (8 KB)
// dynamic smem layout (bytes):
//   xs   : 64*132*4            = 33792
//   bsm  : 3*1024*8            = 24576
//   bias : 512*4               =  2048
//   redmax/redsum: 2*128*4     =  1024
//   bid  : 64*4                =   256
#define SMEM_TOTAL (33792 + 24576 + 2048 + 1024 + 256)

__global__ __launch_bounds__(256) void main_kernel(
    const float* __restrict__ x, const int* __restrict__ batch,
    const float* __restrict__ b_lin, const float* __restrict__ b_gate, int N) {
    extern __shared__ char smraw[];
    uint32_t* xs     = reinterpret_cast<uint32_t*>(smraw);
    uint2*    bsm    = reinterpret_cast<uint2*>(smraw + 33792);
    float*    bias   = reinterpret_cast<float*>(smraw + 33792 + 24576);
    float*    redmax = bias + 512;
    float*    redsum = redmax + 128;
    int*      bid    = reinterpret_cast<int*>(redsum + 128);

    const int tid   = threadIdx.x;
    const int node0 = blockIdx.x * 64;

    const uint32_t bsm_s = (uint32_t)__cvta_generic_to_shared(bsm);

    // prefetch slabs (s=0, kt=0,1) immediately — overlaps with x-tile load
    {
        const char* src0 = (const char*)(g_Bfrag + (size_t)0 * SLAB_U2);
        cp_async16(bsm_s + 0 * 8192 + tid * 16, src0 + tid * 16);
        cp_async16(bsm_s + 0 * 8192 + (tid + 256) * 16, src0 + (tid + 256) * 16);
        cp_commit();
        const char* src1 = (const char*)(g_Bfrag + (size_t)1 * SLAB_U2);
        cp_async16(bsm_s + 1 * 8192 + tid * 16, src1 + tid * 16);
        cp_async16(bsm_s + 1 * 8192 + (tid + 256) * 16, src1 + (tid + 256) * 16);
        cp_commit();
    }

    // load x tile as packed bf16x2 (coalesced float2 reads)
    for (int i = tid; i < 64 * 128; i += 256) {
        int r = i >> 7, cp = i & 127;
        float2 v = make_float2(0.f, 0.f);
        if (node0 + r < N)
            v = reinterpret_cast<const float2*>(x)[(size_t)(node0 + r) * 128 + cp];
        xs[r * XS_STRIDE + cp] = packbf(v.x, v.y);
    }
    bias[tid]       = b_gate[tid];
    bias[256 + tid] = b_lin[tid];
    if (tid < 64) {
        int nd = node0 + tid;
        bid[tid] = (nd < N) ? batch[nd] : -1;
    }
    __syncthreads();

    const int lane = tid & 31, w = tid >> 5;
    const int wr = w >> 1, wc = w & 1;
    const int r0 = wr * 16, gid = lane >> 2, tg = lane & 3;
    const int ra = r0 + gid, rb = ra + 8;
    const int rowA0 = ra * XS_STRIDE;
    const int rowA1 = rb * XS_STRIDE;

    // ================= GEMM 1: gate logits (registers) ======================
    float gate[16][4];
    #pragma unroll
    for (int t = 0; t < 16; t++) { gate[t][0] = gate[t][1] = gate[t][2] = gate[t][3] = 0.f; }
    for (int kt = 0; kt < 16; kt++) {
        cp_wait2();            // slab kt resident
        __syncthreads();       // visible to all; prev user of next buffer done
        int nxt = kt + 2;
        if (nxt < 16) {
            const char* src = (const char*)(g_Bfrag + (size_t)nxt * SLAB_U2);
            uint32_t dst = bsm_s + (nxt % 3) * 8192;
            cp_async16(dst + tid * 16, src + tid * 16);
            cp_async16(dst + (tid + 256) * 16, src + (tid + 256) * 16);
        }
        cp_commit();
        uint32_t a0 = xs[rowA0 + kt * 8 + tg];
        uint32_t a1 = xs[rowA1 + kt * 8 + tg];
        uint32_t a2 = xs[rowA0 + kt * 8 + 4 + tg];
        uint32_t a3 = xs[rowA1 + kt * 8 + 4 + tg];
        const uint2* bp = bsm + (kt % 3) * SLAB_U2 + (wc * 16) * 32 + lane;
        #pragma unroll
        for (int t = 0; t < 16; t++) {
            uint2 bq = bp[t * 32];
            mma_bf16(gate[t], a0, a1, a2, a3, bq.x, bq.y);
        }
    }
    // prefetch first two slabs of GEMM2 (s=1 -> slabs 16,17); overlaps softmax
    __syncthreads();
    {
        const char* src0 = (const char*)(g_Bfrag + (size_t)16 * SLAB_U2);
        cp_async16(bsm_s + (16 % 3) * 8192 + tid * 16, src0 + tid * 16);
        cp_async16(bsm_s + (16 % 3) * 8192 + (tid + 256) * 16, src0 + (tid + 256) * 16);
        cp_commit();
        const char* src1 = (const char*)(g_Bfrag + (size_t)17 * SLAB_U2);
        cp_async16(bsm_s + (17 % 3) * 8192 + tid * 16, src1 + tid * 16);
        cp_async16(bsm_s + (17 % 3) * 8192 + (tid + 256) * 16, src1 + (tid + 256) * 16);
        cp_commit();
    }

    // add gate bias
    #pragma unroll
    for (int t = 0; t < 16; t++) {
        int c = wc * 128 + t * 8 + tg * 2;
        gate[t][0] += bias[c];     gate[t][1] += bias[c + 1];
        gate[t][2] += bias[c];     gate[t][3] += bias[c + 1];
    }

    // ================= cross-warp row softmax ================================
    {
        float mxa = -1e30f, mxb = -1e30f;
        #pragma unroll
        for (int t = 0; t < 16; t++) {
            mxa = fmaxf(mxa, fmaxf(gate[t][0], gate[t][1]));
            mxb = fmaxf(mxb, fmaxf(gate[t][2], gate[t][3]));
        }
        mxa = fmaxf(mxa, __shfl_xor_sync(0xffffffffu, mxa, 1));
        mxa = fmaxf(mxa, __shfl_xor_sync(0xffffffffu, mxa, 2));
        mxb = fmaxf(mxb, __shfl_xor_sync(0xffffffffu, mxb, 1));
        mxb = fmaxf(mxb, __shfl_xor_sync(0xffffffffu, mxb, 2));
        if (tg == 0) { redmax[ra * 2 + wc] = mxa; redmax[rb * 2 + wc] = mxb; }
    }
    __syncthreads();
    float invA, invB;
    {
        float mA = fmaxf(redmax[ra * 2], redmax[ra * 2 + 1]);
        float mB = fmaxf(redmax[rb * 2], redmax[rb * 2 + 1]);
        float sa = 0.f, sb = 0.f;
        #pragma unroll
        for (int t = 0; t < 16; t++) {
            gate[t][0] = __expf(gate[t][0] - mA); sa += gate[t][0];
            gate[t][1] = __expf(gate[t][1] - mA); sa += gate[t][1];
            gate[t][2] = __expf(gate[t][2] - mB); sb += gate[t][2];
            gate[t][3] = __expf(gate[t][3] - mB); sb += gate[t][3];
        }
        sa += __shfl_xor_sync(0xffffffffu, sa, 1);
        sa += __shfl_xor_sync(0xffffffffu, sa, 2);
        sb += __shfl_xor_sync(0xffffffffu, sb, 1);
        sb += __shfl_xor_sync(0xffffffffu, sb, 2);
        if (tg == 0) { redsum[ra * 2 + wc] = sa; redsum[rb * 2 + wc] = sb; }
        __syncthreads();
        invA = 1.f / (redsum[ra * 2] + redsum[ra * 2 + 1]);
        invB = 1.f / (redsum[rb * 2] + redsum[rb * 2 + 1]);
    }

    // ================= GEMM 2: states =======================================
    float acc[16][4];
    #pragma unroll
    for (int t = 0; t < 16; t++) { acc[t][0] = acc[t][1] = acc[t][2] = acc[t][3] = 0.f; }
    for (int kt = 0; kt < 16; kt++) {
        cp_wait2();
        __syncthreads();
        int nxt = kt + 2;
        if (nxt < 16) {
            const char* src = (const char*)(g_Bfrag + (size_t)(16 + nxt) * SLAB_U2);
            uint32_t dst = bsm_s + ((16 + nxt) % 3) * 8192;
            cp_async16(dst + tid * 16, src + tid * 16);
            cp_async16(dst + (tid + 256) * 16, src + (tid + 256) * 16);
        }
        cp_commit();
        uint32_t a0 = xs[rowA0 + kt * 8 + tg];
        uint32_t a1 = xs[rowA1 + kt * 8 + tg];
        uint32_t a2 = xs[rowA0 + kt * 8 + 4 + tg];
        uint32_t a3 = xs[rowA1 + kt * 8 + 4 + tg];
        const uint2* bp = bsm + ((16 + kt) % 3) * SLAB_U2 + (wc * 16) * 32 + lane;
        #pragma unroll
        for (int t = 0; t < 16; t++) {
            uint2 bq = bp[t * 32];
            mma_bf16(acc[t], a0, a1, a2, a3, bq.x, bq.y);
        }
    }
    __syncthreads();   // all warps done reading xs; safe to overwrite

    // gated product, staged into xs as bf16x2
    #pragma unroll
    for (int t = 0; t < 16; t++) {
        int c  = wc * 128 + t * 8 + tg * 2;
        int cp = c >> 1;
        float b0 = bias[256 + c], b1 = bias[256 + c + 1];
        float v0 = (acc[t][0] + b0) * gate[t][0] * invA;
        float v1 = (acc[t][1] + b1) * gate[t][1] * invA;
        float v2 = (acc[t][2] + b0) * gate[t][2] * invB;
        float v3 = (acc[t][3] + b1) * gate[t][3] * invB;
        xs[ra * XS_STRIDE + cp] = packbf(v0, v1);
        xs[rb * XS_STRIDE + cp] = packbf(v2, v3);
    }
    __syncthreads();

    // ================= segment reduce (sorted batch), few atomics ===========
    {
        const int cp = tid >> 1, hi = tid & 1;
        float run = 0.f;
        int cur = -1;
        for (int r = 0; r < 64; r++) {
            int g = bid[r];
            if (g != cur) {
                if (cur >= 0) atomicAdd(&g_sums[cur * CDIM + tid], run);
                run = 0.f;
                cur = g;
            }
            if (g >= 0) {
                uint32_t u = xs[r * XS_STRIDE + cp];
                __nv_bfloat162 h = *reinterpret_cast<__nv_bfloat162*>(&u);
                run += hi ? __bfloat162float(h.y) : __bfloat162float(h.x);
            }
        }
        if (cur >= 0) atomicAdd(&g_sums[cur * CDIM + tid], run);
    }
}

// out[g][c] = b_fin[c] + sum_k (sums[g][k]/max(cnt,1)) * W_fin[k][c]
__global__ void final_kernel(const float* __restrict__ W_fin,
                             const float* __restrict__ b_fin,
                             float* __restrict__ out) {
    __shared__ float mrow[CDIM];
    int g = blockIdx.x, t = threadIdx.x;
    float invc = 1.f / fmaxf((float)g_cnt[g], 1.f);
    mrow[t] = g_sums[g * CDIM + t] * invc;
    __syncthreads();
    float a = b_fin[t];
    #pragma unroll 8
    for (int k = 0; k < CDIM; k++) a = fmaf(mrow[k], W_fin[k * CDIM + t], a);
    out[g * CDIM + t] = a;
}

// ---------------------------------------------------------------------------
extern "C" void kernel_launch(void* const* d_in, const int* in_sizes, int n_in,
                              void* d_out, int out_size) {
    const float* x      = (const float*)d_in[0];
    // d_in[1] = edge_index (int32) : unused by the reference computation
    const int*   batch  = (const int*)d_in[2];     // jax x64 disabled -> int32
    const float* W_lin  = (const float*)d_in[3];
    const float* b_lin  = (const float*)d_in[4];
    const float* W_gate = (const float*)d_in[5];
    const float* b_gate = (const float*)d_in[6];
    const float* W_fin  = (const float*)d_in[7];
    const float* b_fin  = (const float*)d_in[8];
    float*       out    = (float*)d_out;

    int N = in_sizes[0] / CDIM;

    static bool attr_done = false;
    if (!attr_done) {
        cudaFuncSetAttribute(main_kernel, cudaFuncAttributeMaxDynamicSharedMemorySize,
                             SMEM_TOTAL);
        attr_done = true;
    }

    zero_sums_kernel<<<(GRAPHS * CDIM + 255) / 256, 256>>>();
    prep_weights_kernel<<<(2 * 16 * 32 * 32 + 255) / 256, 256>>>(W_gate, W_lin);

    int blocks = (N + 63) / 64;
    main_kernel<<<blocks, 256, SMEM_TOTAL>>>(x, batch, b_lin, b_gate, N);

    counts_kernel<<<4, 128>>>(batch, N);
    final_kernel<<<GRAPHS, CDIM>>>(W_fin, b_fin, out);
}

// round 7
// speedup vs baseline: 1.7388x; 1.4649x over previous
#include <cuda_runtime.h>
#include <cuda_bf16.h>
#include <cstdint>

#define GRAPHS 512
#define CDIM 256

// ---- device scratch (no allocations allowed) ----
__device__ uint2 g_Bfrag[2 * 16 * 32 * 32];   // 256 KB: bf16 B fragments, [s][kt][nt][lane]
__device__ float g_sums[GRAPHS * CDIM];       // 512 KB: pooled sums

static __device__ __forceinline__ uint32_t packbf(float a, float b) {
    __nv_bfloat162 h = __float22bfloat162_rn(make_float2(a, b));
    return *reinterpret_cast<uint32_t*>(&h);
}

// ---------------------------------------------------------------------------
__global__ void zero_sums_kernel() {
    int i = blockIdx.x * blockDim.x + threadIdx.x;
    if (i < GRAPHS * CDIM) g_sums[i] = 0.f;
}

// Pack W_gate (s=0) and W_lin (s=1) into m16n8k16 B-fragment order:
// idx = ((s*16 + kt)*32 + nt)*32 + lane
// n = nt*8 + lane/4, k0 = kt*16 + (lane%4)*2
__global__ void prep_weights_kernel(const float* __restrict__ Wg,
                                    const float* __restrict__ Wl) {
    int i = blockIdx.x * blockDim.x + threadIdx.x;
    if (i >= 2 * 16 * 32 * 32) return;
    int lane = i & 31;
    int nt   = (i >> 5) & 31;
    int kt   = (i >> 10) & 15;
    int s    = i >> 14;
    const float* W = s ? Wl : Wg;
    int n  = nt * 8 + (lane >> 2);
    int k0 = kt * 16 + (lane & 3) * 2;
    uint2 v;
    v.x = packbf(W[(k0 + 0) * CDIM + n], W[(k0 + 1) * CDIM + n]);
    v.y = packbf(W[(k0 + 8) * CDIM + n], W[(k0 + 9) * CDIM + n]);
    g_Bfrag[i] = v;
}

// ---------------------------------------------------------------------------
static __device__ __forceinline__ void mma_bf16(float acc[4],
                                                uint32_t a0, uint32_t a1,
                                                uint32_t a2, uint32_t a3,
                                                uint32_t b0, uint32_t b1) {
    asm volatile(
        "mma.sync.aligned.m16n8k16.row.col.f32.bf16.bf16.f32 "
        "{%0,%1,%2,%3}, {%4,%5,%6,%7}, {%8,%9}, {%0,%1,%2,%3};\n"
        : "+f"(acc[0]), "+f"(acc[1]), "+f"(acc[2]), "+f"(acc[3])
        : "r"(a0), "r"(a1), "r"(a2), "r"(a3), "r"(b0), "r"(b1));
}

static __device__ __forceinline__ void ldsm4(uint32_t& a0, uint32_t& a1,
                                             uint32_t& a2, uint32_t& a3,
                                             uint32_t addr) {
    asm volatile("ldmatrix.sync.aligned.m8n8.x4.shared.b16 {%0,%1,%2,%3}, [%4];"
                 : "=r"(a0), "=r"(a1), "=r"(a2), "=r"(a3) : "r"(addr));
}

static __device__ __forceinline__ void cp_async16(uint32_t smem_dst, const void* gsrc) {
    asm volatile("cp.async.cg.shared.global [%0], [%1], 16;\n"
                 :: "r"(smem_dst), "l"(gsrc));
}
static __device__ __forceinline__ void cp_commit() {
    asm volatile("cp.async.commit_group;\n");
}
static __device__ __forceinline__ void cp_wait2() {
    asm volatile("cp.async.wait_group 2;\n");
}

// Fused: x tile -> bf16 smem -> gate GEMM -> cross-warp softmax (gate staged to
// smem as bf16) -> state GEMM -> gated product -> bf16 staging -> segment
// reduce -> atomics.  B fragments streamed via 3-deep cp.async slab pipeline.
// Block: 64 nodes, 256 threads (8 warps: 4 row-strips x 2 col-halves).
// 2 blocks/SM (95.5 KB smem, <=128 regs via __launch_bounds__(256,2)).
#define XS_STRIDE 132                  // 128 uint32 + 4 pad
#define SLAB_U2   1024                 // 32 nt * 32 lanes, uint2 (8 KB)
// dynamic smem layout (bytes):
#define XS_OFF     0                   // 64*132*4 = 33792
#define BSM_OFF    33792               // 3*8192   = 24576
#define GSM_OFF    58368               // 64*132*4 = 33792 (gate bf16x2)
#define BIAS_OFF   92160               // 512*4    = 2048
#define RMAX_OFF   94208               // 128*4
#define RSUM_OFF   94720               // 128*4
#define BID_OFF    95232               // 64*4
#define SMEM_TOTAL 95488

__global__ __launch_bounds__(256, 2) void main_kernel(
    const float* __restrict__ x, const int* __restrict__ batch,
    const float* __restrict__ b_lin, const float* __restrict__ b_gate, int N) {
    extern __shared__ char smraw[];
    uint32_t* xs     = reinterpret_cast<uint32_t*>(smraw + XS_OFF);
    uint2*    bsm    = reinterpret_cast<uint2*>(smraw + BSM_OFF);
    uint32_t* gsm    = reinterpret_cast<uint32_t*>(smraw + GSM_OFF);
    float*    bias   = reinterpret_cast<float*>(smraw + BIAS_OFF);
    float*    redmax = reinterpret_cast<float*>(smraw + RMAX_OFF);
    float*    redsum = reinterpret_cast<float*>(smraw + RSUM_OFF);
    int*      bid    = reinterpret_cast<int*>(smraw + BID_OFF);

    const int tid   = threadIdx.x;
    const int node0 = blockIdx.x * 64;

    const uint32_t bsm_s = (uint32_t)__cvta_generic_to_shared(bsm);
    const uint32_t xs_s  = (uint32_t)__cvta_generic_to_shared(xs);

    // prefetch slabs (s=0, kt=0,1) immediately — overlaps with x-tile load
    {
        const char* src0 = (const char*)(g_Bfrag + (size_t)0 * SLAB_U2);
        cp_async16(bsm_s + 0 * 8192 + tid * 16, src0 + tid * 16);
        cp_async16(bsm_s + 0 * 8192 + (tid + 256) * 16, src0 + (tid + 256) * 16);
        cp_commit();
        const char* src1 = (const char*)(g_Bfrag + (size_t)1 * SLAB_U2);
        cp_async16(bsm_s + 1 * 8192 + tid * 16, src1 + tid * 16);
        cp_async16(bsm_s + 1 * 8192 + (tid + 256) * 16, src1 + (tid + 256) * 16);
        cp_commit();
    }

    // load x tile as packed bf16x2 (coalesced float2 reads)
    for (int i = tid; i < 64 * 128; i += 256) {
        int r = i >> 7, cp = i & 127;
        float2 v = make_float2(0.f, 0.f);
        if (node0 + r < N)
            v = reinterpret_cast<const float2*>(x)[(size_t)(node0 + r) * 128 + cp];
        xs[r * XS_STRIDE + cp] = packbf(v.x, v.y);
    }
    bias[tid]       = b_gate[tid];
    bias[256 + tid] = b_lin[tid];
    if (tid < 64) {
        int nd = node0 + tid;
        bid[tid] = (nd < N) ? batch[nd] : -1;
    }
    __syncthreads();

    const int lane = tid & 31, w = tid >> 5;
    const int wr = w >> 1, wc = w & 1;
    const int r0 = wr * 16, gid = lane >> 2, tg = lane & 3;
    const int ra = r0 + gid, rb = ra + 8;

    // ldmatrix lane address: m = lane/8 (0..3): m0 rows r0..+7 k0-7,
    // m1 rows r0+8.. k0-7, m2 rows r0.. k8-15, m3 rows r0+8.. k8-15
    const int lrow = r0 + ((lane >> 3) & 1) * 8 + (lane & 7);
    const uint32_t a_addr0 = xs_s + 4u * (uint32_t)(lrow * XS_STRIDE + (lane >> 4) * 4);

    // ================= GEMM 1: gate logits (registers) ======================
    {
        float gate[16][4];
        #pragma unroll
        for (int t = 0; t < 16; t++) { gate[t][0] = gate[t][1] = gate[t][2] = gate[t][3] = 0.f; }
        for (int kt = 0; kt < 16; kt++) {
            cp_wait2();            // slab kt resident
            __syncthreads();       // visible to all; prev user of next buffer done
            int nxt = kt + 2;
            if (nxt < 16) {
                const char* src = (const char*)(g_Bfrag + (size_t)nxt * SLAB_U2);
                uint32_t dst = bsm_s + (nxt % 3) * 8192;
                cp_async16(dst + tid * 16, src + tid * 16);
                cp_async16(dst + (tid + 256) * 16, src + (tid + 256) * 16);
            }
            cp_commit();
            uint32_t a0, a1, a2, a3;
            ldsm4(a0, a1, a2, a3, a_addr0 + (uint32_t)kt * 32);
            const uint2* bp = bsm + (kt % 3) * SLAB_U2 + (wc * 16) * 32 + lane;
            #pragma unroll
            for (int t = 0; t < 16; t++) {
                uint2 bq = bp[t * 32];
                mma_bf16(gate[t], a0, a1, a2, a3, bq.x, bq.y);
            }
        }
        // prefetch first two slabs of GEMM2 (s=1 -> slabs 16,17); overlaps softmax
        __syncthreads();
        {
            const char* src0 = (const char*)(g_Bfrag + (size_t)16 * SLAB_U2);
            cp_async16(bsm_s + (16 % 3) * 8192 + tid * 16, src0 + tid * 16);
            cp_async16(bsm_s + (16 % 3) * 8192 + (tid + 256) * 16, src0 + (tid + 256) * 16);
            cp_commit();
            const char* src1 = (const char*)(g_Bfrag + (size_t)17 * SLAB_U2);
            cp_async16(bsm_s + (17 % 3) * 8192 + tid * 16, src1 + tid * 16);
            cp_async16(bsm_s + (17 % 3) * 8192 + (tid + 256) * 16, src1 + (tid + 256) * 16);
            cp_commit();
        }

        // add gate bias
        #pragma unroll
        for (int t = 0; t < 16; t++) {
            int c = wc * 128 + t * 8 + tg * 2;
            gate[t][0] += bias[c];     gate[t][1] += bias[c + 1];
            gate[t][2] += bias[c];     gate[t][3] += bias[c + 1];
        }

        // ============= cross-warp row softmax; stage exp as bf16 ============
        float mxa = -1e30f, mxb = -1e30f;
        #pragma unroll
        for (int t = 0; t < 16; t++) {
            mxa = fmaxf(mxa, fmaxf(gate[t][0], gate[t][1]));
            mxb = fmaxf(mxb, fmaxf(gate[t][2], gate[t][3]));
        }
        mxa = fmaxf(mxa, __shfl_xor_sync(0xffffffffu, mxa, 1));
        mxa = fmaxf(mxa, __shfl_xor_sync(0xffffffffu, mxa, 2));
        mxb = fmaxf(mxb, __shfl_xor_sync(0xffffffffu, mxb, 1));
        mxb = fmaxf(mxb, __shfl_xor_sync(0xffffffffu, mxb, 2));
        if (tg == 0) { redmax[ra * 2 + wc] = mxa; redmax[rb * 2 + wc] = mxb; }
        __syncthreads();
        float mA = fmaxf(redmax[ra * 2], redmax[ra * 2 + 1]);
        float mB = fmaxf(redmax[rb * 2], redmax[rb * 2 + 1]);
        float sa = 0.f, sb = 0.f;
        #pragma unroll
        for (int t = 0; t < 16; t++) {
            float e0 = __expf(gate[t][0] - mA); sa += e0;
            float e1 = __expf(gate[t][1] - mA); sa += e1;
            float e2 = __expf(gate[t][2] - mB); sb += e2;
            float e3 = __expf(gate[t][3] - mB); sb += e3;
            int cp = (wc * 128 + t * 8 + tg * 2) >> 1;
            gsm[ra * XS_STRIDE + cp] = packbf(e0, e1);
            gsm[rb * XS_STRIDE + cp] = packbf(e2, e3);
        }
        sa += __shfl_xor_sync(0xffffffffu, sa, 1);
        sa += __shfl_xor_sync(0xffffffffu, sa, 2);
        sb += __shfl_xor_sync(0xffffffffu, sb, 1);
        sb += __shfl_xor_sync(0xffffffffu, sb, 2);
        if (tg == 0) { redsum[ra * 2 + wc] = sa; redsum[rb * 2 + wc] = sb; }
        __syncthreads();
    }
    const float invA = 1.f / (redsum[ra * 2] + redsum[ra * 2 + 1]);
    const float invB = 1.f / (redsum[rb * 2] + redsum[rb * 2 + 1]);

    // ================= GEMM 2: states =======================================
    float acc[16][4];
    #pragma unroll
    for (int t = 0; t < 16; t++) { acc[t][0] = acc[t][1] = acc[t][2] = acc[t][3] = 0.f; }
    for (int kt = 0; kt < 16; kt++) {
        cp_wait2();
        __syncthreads();
        int nxt = kt + 2;
        if (nxt < 16) {
            const char* src = (const char*)(g_Bfrag + (size_t)(16 + nxt) * SLAB_U2);
            uint32_t dst = bsm_s + ((16 + nxt) % 3) * 8192;
            cp_async16(dst + tid * 16, src + tid * 16);
            cp_async16(dst + (tid + 256) * 16, src + (tid + 256) * 16);
        }
        cp_commit();
        uint32_t a0, a1, a2, a3;
        ldsm4(a0, a1, a2, a3, a_addr0 + (uint32_t)kt * 32);
        const uint2* bp = bsm + ((16 + kt) % 3) * SLAB_U2 + (wc * 16) * 32 + lane;
        #pragma unroll
        for (int t = 0; t < 16; t++) {
            uint2 bq = bp[t * 32];
            mma_bf16(acc[t], a0, a1, a2, a3, bq.x, bq.y);
        }
    }
    __syncthreads();   // all warps done reading xs; safe to overwrite

    // gated product (gate read back from gsm, own values), staged into xs bf16x2
    #pragma unroll
    for (int t = 0; t < 16; t++) {
        int c  = wc * 128 + t * 8 + tg * 2;
        int cp = c >> 1;
        float b0 = bias[256 + c], b1 = bias[256 + c + 1];
        uint32_t ga = gsm[ra * XS_STRIDE + cp];
        uint32_t gb = gsm[rb * XS_STRIDE + cp];
        __nv_bfloat162 ha = *reinterpret_cast<__nv_bfloat162*>(&ga);
        __nv_bfloat162 hb = *reinterpret_cast<__nv_bfloat162*>(&gb);
        float v0 = (acc[t][0] + b0) * __bfloat162float(ha.x) * invA;
        float v1 = (acc[t][1] + b1) * __bfloat162float(ha.y) * invA;
        float v2 = (acc[t][2] + b0) * __bfloat162float(hb.x) * invB;
        float v3 = (acc[t][3] + b1) * __bfloat162float(hb.y) * invB;
        xs[ra * XS_STRIDE + cp] = packbf(v0, v1);
        xs[rb * XS_STRIDE + cp] = packbf(v2, v3);
    }
    __syncthreads();

    // ================= segment reduce (sorted batch), few atomics ===========
    {
        const int cp = tid >> 1, hi = tid & 1;
        float run = 0.f;
        int cur = -1;
        for (int r = 0; r < 64; r++) {
            int g = bid[r];
            if (g != cur) {
                if (cur >= 0) atomicAdd(&g_sums[cur * CDIM + tid], run);
                run = 0.f;
                cur = g;
            }
            if (g >= 0) {
                uint32_t u = xs[r * XS_STRIDE + cp];
                __nv_bfloat162 h = *reinterpret_cast<__nv_bfloat162*>(&u);
                run += hi ? __bfloat162float(h.y) : __bfloat162float(h.x);
            }
        }
        if (cur >= 0) atomicAdd(&g_sums[cur * CDIM + tid], run);
    }
}

// out[g][c] = b_fin[c] + sum_k (sums[g][k]/max(cnt,1)) * W_fin[k][c]
// count computed per-block via binary search on sorted batch (L2-hot).
__global__ void final_kernel(const int* __restrict__ batch, int N,
                             const float* __restrict__ W_fin,
                             const float* __restrict__ b_fin,
                             float* __restrict__ out) {
    __shared__ float mrow[CDIM];
    __shared__ int bounds[2];
    int g = blockIdx.x, t = threadIdx.x;
    if (t < 2) {
        int key = g + t;     // t=0: lower bound of g ; t=1: lower bound of g+1
        int lo = 0, hi = N;
        while (lo < hi) { int m = (lo + hi) >> 1; if (batch[m] < key) lo = m + 1; else hi = m; }
        bounds[t] = lo;
    }
    __syncthreads();
    float invc = 1.f / fmaxf((float)(bounds[1] - bounds[0]), 1.f);
    mrow[t] = g_sums[g * CDIM + t] * invc;
    __syncthreads();
    float a = b_fin[t];
    #pragma unroll 8
    for (int k = 0; k < CDIM; k++) a = fmaf(mrow[k], W_fin[k * CDIM + t], a);
    out[g * CDIM + t] = a;
}

// ---------------------------------------------------------------------------
extern "C" void kernel_launch(void* const* d_in, const int* in_sizes, int n_in,
                              void* d_out, int out_size) {
    const float* x      = (const float*)d_in[0];
    // d_in[1] = edge_index (int32) : unused by the reference computation
    const int*   batch  = (const int*)d_in[2];     // jax x64 disabled -> int32
    const float* W_lin  = (const float*)d_in[3];
    const float* b_lin  = (const float*)d_in[4];
    const float* W_gate = (const float*)d_in[5];
    const float* b_gate = (const float*)d_in[6];
    const float* W_fin  = (const float*)d_in[7];
    const float* b_fin  = (const float*)d_in[8];
    float*       out    = (float*)d_out;

    int N = in_sizes[0] / CDIM;

    static bool attr_done = false;
    if (!attr_done) {
        cudaFuncSetAttribute(main_kernel, cudaFuncAttributeMaxDynamicSharedMemorySize,
                             SMEM_TOTAL);
        attr_done = true;
    }

    zero_sums_kernel<<<(GRAPHS * CDIM + 255) / 256, 256>>>();
    prep_weights_kernel<<<(2 * 16 * 32 * 32 + 255) / 256, 256>>>(W_gate, W_lin);

    int blocks = (N + 63) / 64;
    main_kernel<<<blocks, 256, SMEM_TOTAL>>>(x, batch, b_lin, b_gate, N);

    final_kernel<<<GRAPHS, CDIM>>>(batch, N, W_fin, b_fin, out);
}

// round 8
// speedup vs baseline: 1.9206x; 1.1046x over previous
#include <cuda_runtime.h>
#include <cuda_bf16.h>
#include <cstdint>

#define GRAPHS 512
#define CDIM 256

// ---- device scratch (no allocations allowed) ----
// B fragments packed as uint4: [s][kt][ntp][lane], ntp = nt/2 pairs (2 n-tiles)
__device__ uint4 g_Bfrag[2 * 16 * 16 * 32];   // 256 KB
__device__ float g_sums[GRAPHS * CDIM];       // 512 KB: pooled sums

static __device__ __forceinline__ uint32_t packbf(float a, float b) {
    __nv_bfloat162 h = __float22bfloat162_rn(make_float2(a, b));
    return *reinterpret_cast<uint32_t*>(&h);
}

// ---------------------------------------------------------------------------
__global__ void zero_sums_kernel() {
    int i = blockIdx.x * blockDim.x + threadIdx.x;
    if (i < GRAPHS * CDIM) g_sums[i] = 0.f;
}

// Pack W_gate (s=0) and W_lin (s=1) into paired m16n8k16 B fragments:
// idx = ((s*16 + kt)*16 + ntp)*32 + lane ; covers n-tiles 2*ntp and 2*ntp+1.
// n = nt*8 + lane/4, k0 = kt*16 + (lane%4)*2
__global__ void prep_weights_kernel(const float* __restrict__ Wg,
                                    const float* __restrict__ Wl) {
    int i = blockIdx.x * blockDim.x + threadIdx.x;
    if (i >= 2 * 16 * 16 * 32) return;
    int lane = i & 31;
    int ntp  = (i >> 5) & 15;
    int kt   = (i >> 9) & 15;
    int s    = i >> 13;
    const float* W = s ? Wl : Wg;
    int n0 = (2 * ntp) * 8 + (lane >> 2);
    int n1 = n0 + 8;
    int k0 = kt * 16 + (lane & 3) * 2;
    uint4 v;
    v.x = packbf(W[(k0 + 0) * CDIM + n0], W[(k0 + 1) * CDIM + n0]);
    v.y = packbf(W[(k0 + 8) * CDIM + n0], W[(k0 + 9) * CDIM + n0]);
    v.z = packbf(W[(k0 + 0) * CDIM + n1], W[(k0 + 1) * CDIM + n1]);
    v.w = packbf(W[(k0 + 8) * CDIM + n1], W[(k0 + 9) * CDIM + n1]);
    g_Bfrag[i] = v;
}

// ---------------------------------------------------------------------------
static __device__ __forceinline__ void mma_bf16(float acc[4],
                                                uint32_t a0, uint32_t a1,
                                                uint32_t a2, uint32_t a3,
                                                uint32_t b0, uint32_t b1) {
    asm volatile(
        "mma.sync.aligned.m16n8k16.row.col.f32.bf16.bf16.f32 "
        "{%0,%1,%2,%3}, {%4,%5,%6,%7}, {%8,%9}, {%0,%1,%2,%3};\n"
        : "+f"(acc[0]), "+f"(acc[1]), "+f"(acc[2]), "+f"(acc[3])
        : "r"(a0), "r"(a1), "r"(a2), "r"(a3), "r"(b0), "r"(b1));
}

static __device__ __forceinline__ void ldsm4(uint32_t& a0, uint32_t& a1,
                                             uint32_t& a2, uint32_t& a3,
                                             uint32_t addr) {
    asm volatile("ldmatrix.sync.aligned.m8n8.x4.shared.b16 {%0,%1,%2,%3}, [%4];"
                 : "=r"(a0), "=r"(a1), "=r"(a2), "=r"(a3) : "r"(addr));
}

static __device__ __forceinline__ void cp_async16(uint32_t smem_dst, const void* gsrc) {
    asm volatile("cp.async.cg.shared.global [%0], [%1], 16;\n"
                 :: "r"(smem_dst), "l"(gsrc));
}
static __device__ __forceinline__ void cp_commit() {
    asm volatile("cp.async.commit_group;\n");
}
static __device__ __forceinline__ void cp_wait2() {
    asm volatile("cp.async.wait_group 2;\n");
}

// Fused pipeline. Warp tile: 32 rows (2 x m16) x 64 cols (8 n-tiles).
// Block: 64 nodes, 256 threads = 2 row-groups x 4 col-quarters.
// B smem traffic halved vs R7 (each B fragment feeds 2 row strips), and B
// loads are LDS.128 (paired n-tiles).
#define XS_STRIDE 132                  // 128 uint32 + 4 pad
#define SLAB_U4   512                  // 16 ntp * 32 lanes, uint4 (8 KB)
// dynamic smem layout (bytes):
#define XS_OFF     0                   // 64*132*4 = 33792
#define BSM_OFF    33792               // 3*8192   = 24576
#define GSM_OFF    58368               // 64*132*4 = 33792 (gate exp bf16x2)
#define BIAS_OFF   92160               // 512*4    = 2048
#define RMAX_OFF   94208               // 256*4
#define RSUM_OFF   95232               // 256*4
#define BID_OFF    96256               // 64*4
#define SMEM_TOTAL 96512

__global__ __launch_bounds__(256, 2) void main_kernel(
    const float* __restrict__ x, const int* __restrict__ batch,
    const float* __restrict__ b_lin, const float* __restrict__ b_gate, int N) {
    extern __shared__ char smraw[];
    uint32_t* xs     = reinterpret_cast<uint32_t*>(smraw + XS_OFF);
    uint4*    bsm    = reinterpret_cast<uint4*>(smraw + BSM_OFF);
    uint32_t* gsm    = reinterpret_cast<uint32_t*>(smraw + GSM_OFF);
    float*    bias   = reinterpret_cast<float*>(smraw + BIAS_OFF);
    float*    redmax = reinterpret_cast<float*>(smraw + RMAX_OFF);
    float*    redsum = reinterpret_cast<float*>(smraw + RSUM_OFF);
    int*      bid    = reinterpret_cast<int*>(smraw + BID_OFF);

    const int tid   = threadIdx.x;
    const int node0 = blockIdx.x * 64;

    const uint32_t bsm_s = (uint32_t)__cvta_generic_to_shared(bsm);
    const uint32_t xs_s  = (uint32_t)__cvta_generic_to_shared(xs);

    // prefetch slabs (s=0, kt=0,1) immediately — overlaps with x-tile load
    {
        const char* src0 = (const char*)(g_Bfrag + (size_t)0 * SLAB_U4);
        cp_async16(bsm_s + 0 * 8192 + tid * 16, src0 + tid * 16);
        cp_async16(bsm_s + 0 * 8192 + (tid + 256) * 16, src0 + (tid + 256) * 16);
        cp_commit();
        const char* src1 = (const char*)(g_Bfrag + (size_t)1 * SLAB_U4);
        cp_async16(bsm_s + 1 * 8192 + tid * 16, src1 + tid * 16);
        cp_async16(bsm_s + 1 * 8192 + (tid + 256) * 16, src1 + (tid + 256) * 16);
        cp_commit();
    }

    // load x tile as packed bf16x2 (coalesced float2 reads)
    for (int i = tid; i < 64 * 128; i += 256) {
        int r = i >> 7, cp = i & 127;
        float2 v = make_float2(0.f, 0.f);
        if (node0 + r < N)
            v = reinterpret_cast<const float2*>(x)[(size_t)(node0 + r) * 128 + cp];
        xs[r * XS_STRIDE + cp] = packbf(v.x, v.y);
    }
    bias[tid]       = b_gate[tid];
    bias[256 + tid] = b_lin[tid];
    if (tid < 64) {
        int nd = node0 + tid;
        bid[tid] = (nd < N) ? batch[nd] : -1;
    }
    __syncthreads();

    const int lane = tid & 31, w = tid >> 5;
    const int wr = w >> 2;                // row group 0..1
    const int wq = w & 3;                 // column quarter 0..3
    const int r0 = wr * 32, gid = lane >> 2, tg = lane & 3;
    // 4 rows owned per thread (2 strips x {ra, rb})
    const int ra0 = r0 + gid,      rb0 = ra0 + 8;
    const int ra1 = r0 + 16 + gid, rb1 = ra1 + 8;

    // ldmatrix lane addresses for both strips
    const int lr = ((lane >> 3) & 1) * 8 + (lane & 7);
    const uint32_t a_addr0 = xs_s + 4u * (uint32_t)((r0 + lr) * XS_STRIDE + (lane >> 4) * 4);
    const uint32_t a_addr1 = xs_s + 4u * (uint32_t)((r0 + 16 + lr) * XS_STRIDE + (lane >> 4) * 4);

    float invr[4];   // 1/sum for ra0, rb0, ra1, rb1

    // ================= GEMM 1: gate logits ==================================
    {
        float gate[2][8][4];
        #pragma unroll
        for (int s = 0; s < 2; s++)
            #pragma unroll
            for (int t = 0; t < 8; t++)
                gate[s][t][0] = gate[s][t][1] = gate[s][t][2] = gate[s][t][3] = 0.f;
        for (int kt = 0; kt < 16; kt++) {
            cp_wait2();
            __syncthreads();
            int nxt = kt + 2;
            if (nxt < 16) {
                const char* src = (const char*)(g_Bfrag + (size_t)nxt * SLAB_U4);
                uint32_t dst = bsm_s + (nxt % 3) * 8192;
                cp_async16(dst + tid * 16, src + tid * 16);
                cp_async16(dst + (tid + 256) * 16, src + (tid + 256) * 16);
            }
            cp_commit();
            uint32_t a0, a1, a2, a3, c0, c1, c2, c3;
            ldsm4(a0, a1, a2, a3, a_addr0 + (uint32_t)kt * 32);
            ldsm4(c0, c1, c2, c3, a_addr1 + (uint32_t)kt * 32);
            const uint4* bp = bsm + (kt % 3) * SLAB_U4 + (wq * 4) * 32 + lane;
            #pragma unroll
            for (int j = 0; j < 4; j++) {
                uint4 bq = bp[j * 32];
                mma_bf16(gate[0][2 * j],     a0, a1, a2, a3, bq.x, bq.y);
                mma_bf16(gate[0][2 * j + 1], a0, a1, a2, a3, bq.z, bq.w);
                mma_bf16(gate[1][2 * j],     c0, c1, c2, c3, bq.x, bq.y);
                mma_bf16(gate[1][2 * j + 1], c0, c1, c2, c3, bq.z, bq.w);
            }
        }
        __syncthreads();
        // prefetch first two slabs of GEMM2 (s=1 -> slabs 16,17)
        {
            const char* src0 = (const char*)(g_Bfrag + (size_t)16 * SLAB_U4);
            cp_async16(bsm_s + (16 % 3) * 8192 + tid * 16, src0 + tid * 16);
            cp_async16(bsm_s + (16 % 3) * 8192 + (tid + 256) * 16, src0 + (tid + 256) * 16);
            cp_commit();
            const char* src1 = (const char*)(g_Bfrag + (size_t)17 * SLAB_U4);
            cp_async16(bsm_s + (17 % 3) * 8192 + tid * 16, src1 + tid * 16);
            cp_async16(bsm_s + (17 % 3) * 8192 + (tid + 256) * 16, src1 + (tid + 256) * 16);
            cp_commit();
        }

        // bias + per-thread max over its columns, per row
        float mx[4] = {-1e30f, -1e30f, -1e30f, -1e30f};
        #pragma unroll
        for (int s = 0; s < 2; s++)
            #pragma unroll
            for (int t = 0; t < 8; t++) {
                int c = wq * 64 + t * 8 + tg * 2;
                gate[s][t][0] += bias[c];     gate[s][t][1] += bias[c + 1];
                gate[s][t][2] += bias[c];     gate[s][t][3] += bias[c + 1];
                mx[2 * s]     = fmaxf(mx[2 * s],     fmaxf(gate[s][t][0], gate[s][t][1]));
                mx[2 * s + 1] = fmaxf(mx[2 * s + 1], fmaxf(gate[s][t][2], gate[s][t][3]));
            }
        #pragma unroll
        for (int q = 0; q < 4; q++) {
            mx[q] = fmaxf(mx[q], __shfl_xor_sync(0xffffffffu, mx[q], 1));
            mx[q] = fmaxf(mx[q], __shfl_xor_sync(0xffffffffu, mx[q], 2));
        }
        if (tg == 0) {
            redmax[ra0 * 4 + wq] = mx[0];
            redmax[rb0 * 4 + wq] = mx[1];
            redmax[ra1 * 4 + wq] = mx[2];
            redmax[rb1 * 4 + wq] = mx[3];
        }
        __syncthreads();
        const int rows[4] = {ra0, rb0, ra1, rb1};
        float m[4], sum[4] = {0.f, 0.f, 0.f, 0.f};
        #pragma unroll
        for (int q = 0; q < 4; q++) {
            float* rm = &redmax[rows[q] * 4];
            m[q] = fmaxf(fmaxf(rm[0], rm[1]), fmaxf(rm[2], rm[3]));
        }
        #pragma unroll
        for (int s = 0; s < 2; s++)
            #pragma unroll
            for (int t = 0; t < 8; t++) {
                float e0 = __expf(gate[s][t][0] - m[2 * s]);
                float e1 = __expf(gate[s][t][1] - m[2 * s]);
                float e2 = __expf(gate[s][t][2] - m[2 * s + 1]);
                float e3 = __expf(gate[s][t][3] - m[2 * s + 1]);
                sum[2 * s]     += e0 + e1;
                sum[2 * s + 1] += e2 + e3;
                int cp = (wq * 64 + t * 8 + tg * 2) >> 1;
                gsm[rows[2 * s]     * XS_STRIDE + cp] = packbf(e0, e1);
                gsm[rows[2 * s + 1] * XS_STRIDE + cp] = packbf(e2, e3);
            }
        #pragma unroll
        for (int q = 0; q < 4; q++) {
            sum[q] += __shfl_xor_sync(0xffffffffu, sum[q], 1);
            sum[q] += __shfl_xor_sync(0xffffffffu, sum[q], 2);
        }
        if (tg == 0) {
            redsum[ra0 * 4 + wq] = sum[0];
            redsum[rb0 * 4 + wq] = sum[1];
            redsum[ra1 * 4 + wq] = sum[2];
            redsum[rb1 * 4 + wq] = sum[3];
        }
        __syncthreads();
        #pragma unroll
        for (int q = 0; q < 4; q++) {
            float* rs = &redsum[rows[q] * 4];
            invr[q] = 1.f / (rs[0] + rs[1] + rs[2] + rs[3]);
        }
    }

    // ================= GEMM 2: states =======================================
    float acc[2][8][4];
    #pragma unroll
    for (int s = 0; s < 2; s++)
        #pragma unroll
        for (int t = 0; t < 8; t++)
            acc[s][t][0] = acc[s][t][1] = acc[s][t][2] = acc[s][t][3] = 0.f;
    for (int kt = 0; kt < 16; kt++) {
        cp_wait2();
        __syncthreads();
        int nxt = kt + 2;
        if (nxt < 16) {
            const char* src = (const char*)(g_Bfrag + (size_t)(16 + nxt) * SLAB_U4);
            uint32_t dst = bsm_s + ((16 + nxt) % 3) * 8192;
            cp_async16(dst + tid * 16, src + tid * 16);
            cp_async16(dst + (tid + 256) * 16, src + (tid + 256) * 16);
        }
        cp_commit();
        uint32_t a0, a1, a2, a3, c0, c1, c2, c3;
        ldsm4(a0, a1, a2, a3, a_addr0 + (uint32_t)kt * 32);
        ldsm4(c0, c1, c2, c3, a_addr1 + (uint32_t)kt * 32);
        const uint4* bp = bsm + ((16 + kt) % 3) * SLAB_U4 + (wq * 4) * 32 + lane;
        #pragma unroll
        for (int j = 0; j < 4; j++) {
            uint4 bq = bp[j * 32];
            mma_bf16(acc[0][2 * j],     a0, a1, a2, a3, bq.x, bq.y);
            mma_bf16(acc[0][2 * j + 1], a0, a1, a2, a3, bq.z, bq.w);
            mma_bf16(acc[1][2 * j],     c0, c1, c2, c3, bq.x, bq.y);
            mma_bf16(acc[1][2 * j + 1], c0, c1, c2, c3, bq.z, bq.w);
        }
    }
    __syncthreads();   // all warps done reading xs; safe to overwrite

    // gated product (gate exp read back from gsm), staged into xs bf16x2
    {
        const int rows[4] = {ra0, rb0, ra1, rb1};
        #pragma unroll
        for (int s = 0; s < 2; s++)
            #pragma unroll
            for (int t = 0; t < 8; t++) {
                int c  = wq * 64 + t * 8 + tg * 2;
                int cp = c >> 1;
                float b0 = bias[256 + c], b1 = bias[256 + c + 1];
                uint32_t ga = gsm[rows[2 * s]     * XS_STRIDE + cp];
                uint32_t gb = gsm[rows[2 * s + 1] * XS_STRIDE + cp];
                __nv_bfloat162 ha = *reinterpret_cast<__nv_bfloat162*>(&ga);
                __nv_bfloat162 hb = *reinterpret_cast<__nv_bfloat162*>(&gb);
                float v0 = (acc[s][t][0] + b0) * __bfloat162float(ha.x) * invr[2 * s];
                float v1 = (acc[s][t][1] + b1) * __bfloat162float(ha.y) * invr[2 * s];
                float v2 = (acc[s][t][2] + b0) * __bfloat162float(hb.x) * invr[2 * s + 1];
                float v3 = (acc[s][t][3] + b1) * __bfloat162float(hb.y) * invr[2 * s + 1];
                xs[rows[2 * s]     * XS_STRIDE + cp] = packbf(v0, v1);
                xs[rows[2 * s + 1] * XS_STRIDE + cp] = packbf(v2, v3);
            }
    }
    __syncthreads();

    // ================= segment reduce (sorted batch), few atomics ===========
    {
        const int cp = tid >> 1, hi = tid & 1;
        float run = 0.f;
        int cur = -1;
        for (int r = 0; r < 64; r++) {
            int g = bid[r];
            if (g != cur) {
                if (cur >= 0) atomicAdd(&g_sums[cur * CDIM + tid], run);
                run = 0.f;
                cur = g;
            }
            if (g >= 0) {
                uint32_t u = xs[r * XS_STRIDE + cp];
                __nv_bfloat162 h = *reinterpret_cast<__nv_bfloat162*>(&u);
                run += hi ? __bfloat162float(h.y) : __bfloat162float(h.x);
            }
        }
        if (cur >= 0) atomicAdd(&g_sums[cur * CDIM + tid], run);
    }
}

// out[g][c] = b_fin[c] + sum_k (sums[g][k]/max(cnt,1)) * W_fin[k][c]
// count computed per-block via binary search on sorted batch (L2-hot).
__global__ void final_kernel(const int* __restrict__ batch, int N,
                             const float* __restrict__ W_fin,
                             const float* __restrict__ b_fin,
                             float* __restrict__ out) {
    __shared__ float mrow[CDIM];
    __shared__ int bounds[2];
    int g = blockIdx.x, t = threadIdx.x;
    if (t < 2) {
        int key = g + t;
        int lo = 0, hi = N;
        while (lo < hi) { int m = (lo + hi) >> 1; if (batch[m] < key) lo = m + 1; else hi = m; }
        bounds[t] = lo;
    }
    __syncthreads();
    float invc = 1.f / fmaxf((float)(bounds[1] - bounds[0]), 1.f);
    mrow[t] = g_sums[g * CDIM + t] * invc;
    __syncthreads();
    float a = b_fin[t];
    #pragma unroll 8
    for (int k = 0; k < CDIM; k++) a = fmaf(mrow[k], W_fin[k * CDIM + t], a);
    out[g * CDIM + t] = a;
}

// ---------------------------------------------------------------------------
extern "C" void kernel_launch(void* const* d_in, const int* in_sizes, int n_in,
                              void* d_out, int out_size) {
    const float* x      = (const float*)d_in[0];
    // d_in[1] = edge_index (int32) : unused by the reference computation
    const int*   batch  = (const int*)d_in[2];     // jax x64 disabled -> int32
    const float* W_lin  = (const float*)d_in[3];
    const float* b_lin  = (const float*)d_in[4];
    const float* W_gate = (const float*)d_in[5];
    const float* b_gate = (const float*)d_in[6];
    const float* W_fin  = (const float*)d_in[7];
    const float* b_fin  = (const float*)d_in[8];
    float*       out    = (float*)d_out;

    int N = in_sizes[0] / CDIM;

    static bool attr_done = false;
    if (!attr_done) {
        cudaFuncSetAttribute(main_kernel, cudaFuncAttributeMaxDynamicSharedMemorySize,
                             SMEM_TOTAL);
        attr_done = true;
    }

    zero_sums_kernel<<<(GRAPHS * CDIM + 255) / 256, 256>>>();
    prep_weights_kernel<<<(2 * 16 * 16 * 32 + 255) / 256, 256>>>(W_gate, W_lin);

    int blocks = (N + 63) / 64;
    main_kernel<<<blocks, 256, SMEM_TOTAL>>>(x, batch, b_lin, b_gate, N);

    final_kernel<<<GRAPHS, CDIM>>>(batch, N, W_fin, b_fin, out);
}